// round 11
// baseline (speedup 1.0000x reference)
#include <cuda_runtime.h>
#include <cuda_fp16.h>
#include <math.h>
#include <cstdint>

#define B_ 8
#define N_ 8192
#define K_ 32
#define D_ 64

typedef unsigned long long ull;

// ---------------- dynamic smem byte offsets ----------------
#define OFF_BFRAG   0          // B frags: 24 combos x (hi 1024B + lo 1024B), lo scaled x256; W1,W2 pre-halved
#define OFF_AGH     49152      // 256 rows x 34 uint (fp16x2 gathered src), 34816B ; UPD aliases this
#define OFF_SSELF   83968      // 8 x 64 f32 (emb*mask per node)
#define OFF_SELFC   86016      // 8 x 64 f32 (b0 + self-part of layer 0, precomputed)
#define OFF_SDIST   88064      // 256 f32
#define OFF_SVALID  89088      // 256 f32
#define OFF_SIDX    90112      // 256 i32
#define OFF_WD      91136      // 64 f32 (W0[:,128] dist column)
#define OFF_B1S     91392      // 64 f32
#define OFF_B2S     91648      // 64 f32
#define OFF_FACT    91904      // 8 f32 (mask*0.5/n_valid)
#define OFF_PART    91936      // 8 nodes x 64 f32 full per-node message sums
#define OFF_SACC    93984      // 8 b x 64 d x 2 f32 block-local stats accumulators
#define SMEM_BYTES  98304

#define OFF_UPD     OFF_AGH    // 1024 f32 staging (aliases AGH, dead by then)

// ---------------- device scratch ----------------
__device__ float g_upd[B_ * N_ * D_];
__device__ float g_selfc[B_ * N_ * D_];
__device__ float g_sum[B_][D_];
__device__ float g_sqs[B_][D_];
__device__ float g_cnt[B_];

// ---------------- packed f32x2 helpers ----------------
__device__ __forceinline__ ull pk2(float a, float b) {
    ull r; asm("mov.b64 %0, {%1, %2};" : "=l"(r) : "f"(a), "f"(b)); return r;
}
__device__ __forceinline__ void upk2(ull v, float& a, float& b) {
    asm("mov.b64 {%0, %1}, %2;" : "=f"(a), "=f"(b) : "l"(v));
}
__device__ __forceinline__ ull f2mul(ull a, ull b) {
    ull r; asm("mul.rn.f32x2 %0, %1, %2;" : "=l"(r) : "l"(a), "l"(b)); return r;
}
__device__ __forceinline__ ull f2fma(ull a, ull b, ull c) {
    ull r; asm("fma.rn.f32x2 %0, %1, %2, %3;" : "=l"(r) : "l"(a), "l"(b), "l"(c)); return r;
}

// packed gelu constants
struct GP { ull C1, C2; };

// packed 2*gelu(x): x * (1 + tanh(0.79788456*x + 0.03567741*x^3)), hw tanh
__device__ __forceinline__ ull gelu2x_pk(ull x, const GP& K) {
    ull xx = f2mul(x, x);
    ull c  = f2fma(xx, K.C2, K.C1);
    ull u  = f2mul(c, x);
    float u0, u1; upk2(u, u0, u1);
    float t0, t1;
    asm("tanh.approx.f32 %0, %1;" : "=f"(t0) : "f"(u0));
    asm("tanh.approx.f32 %0, %1;" : "=f"(t1) : "f"(u1));
    ull t = pk2(t0, t1);
    return f2fma(x, t, x);
}

__device__ __forceinline__ uint32_t pack_f16x2(float lo, float hi) {
    uint32_t r;
    asm("cvt.rn.f16x2.f32 %0, %1, %2;" : "=r"(r) : "f"(hi), "f"(lo));
    return r;
}
__device__ __forceinline__ uint32_t pk_to_f16(ull v) {
    float a, b; upk2(v, a, b);
    return pack_f16x2(a, b);
}

__device__ __forceinline__ void mma_f16(float* d,
                                        uint32_t a0, uint32_t a1, uint32_t a2, uint32_t a3,
                                        uint32_t b0, uint32_t b1) {
    asm volatile(
        "mma.sync.aligned.m16n8k16.row.col.f32.f16.f16.f32 "
        "{%0,%1,%2,%3}, {%4,%5,%6,%7}, {%8,%9}, {%0,%1,%2,%3};"
        : "+f"(d[0]), "+f"(d[1]), "+f"(d[2]), "+f"(d[3])
        : "r"(a0), "r"(a1), "r"(a2), "r"(a3), "r"(b0), "r"(b1));
}

__global__ void __launch_bounds__(128, 2)
mpnn_msg_kernel(const float* __restrict__ emb,
                const float* __restrict__ dists,
                const int*   __restrict__ eidx,
                const float* __restrict__ mask,
                const float* __restrict__ W0, const float* __restrict__ b0,
                const float* __restrict__ W1, const float* __restrict__ b1,
                const float* __restrict__ W2, const float* __restrict__ b2)
{
    extern __shared__ char smb[];
    float* smf = reinterpret_cast<float*>(smb);
    const int tid = threadIdx.x;
    const int w = tid >> 5, lane = tid & 31;   // 4 warps
    const int lq = lane >> 2;      // 0..7 (row group)
    const int lr = lane & 3;       // 0..3 (col pair group)

    GP K;
    K.C1 = pk2(0.7978845608f, 0.7978845608f);
    K.C2 = pk2(0.03567740814f, 0.03567740814f);

    // ---- one-time staging: B fragments (fp16 hi + lo*256), wd, biases ----
    for (int c = w; c < 24; c += 4) {
        const int l = c >> 3, t = c & 7;
        const float* W = (l == 0) ? W0 : (l == 1) ? W1 : W2;
        const int stride = (l == 0) ? 129 : 64;
        const float wsc = (l == 0) ? 1.0f : 0.5f;
        const int n = t * 8 + lq;
        uint32_t hi[8], lo[8];
#pragma unroll
        for (int j = 0; j < 8; j++) {
            int s = j >> 1, rsel = j & 1;
            int k = 16 * s + 8 * rsel + 2 * lr;
            float x0 = W[n * stride + k] * wsc;
            float x1 = W[n * stride + k + 1] * wsc;
            uint32_t h = pack_f16x2(x0, x1);
            __half2 hh = *reinterpret_cast<__half2*>(&h);
            float r0f = x0 - __low2float(hh);
            float r1f = x1 - __high2float(hh);
            hi[j] = h;
            lo[j] = pack_f16x2(r0f * 256.0f, r1f * 256.0f);
        }
        uint4* dh = reinterpret_cast<uint4*>(smb + OFF_BFRAG + c * 2048 + lane * 32);
        uint4* dl = reinterpret_cast<uint4*>(smb + OFF_BFRAG + c * 2048 + 1024 + lane * 32);
        dh[0] = make_uint4(hi[0], hi[1], hi[2], hi[3]);
        dh[1] = make_uint4(hi[4], hi[5], hi[6], hi[7]);
        dl[0] = make_uint4(lo[0], lo[1], lo[2], lo[3]);
        dl[1] = make_uint4(lo[4], lo[5], lo[6], lo[7]);
    }
    if (tid < 64) {
        smf[OFF_WD / 4 + tid]  = W0[tid * 129 + 128];
        smf[OFF_B1S / 4 + tid] = b1[tid];
        smf[OFF_B2S / 4 + tid] = b2[tid];
    }
    for (int p = tid; p < 1024; p += 128) smf[OFF_SACC / 4 + p] = 0.0f;
    __syncthreads();

    int* sIdx = reinterpret_cast<int*>(smb + OFF_SIDX);
    const int totalTiles = (B_ * N_) / 8;   // 8 nodes x 32 edges = 256 rows/tile

    for (int tile = blockIdx.x; tile < totalTiles; tile += gridDim.x) {
        const int bn0 = tile << 3;
        const int b   = bn0 >> 13;
        const int n0  = bn0 & (N_ - 1);
        const int bbase = b * N_;

        // ---- phase 1: edge meta + self emb + precomputed selfC ----
#pragma unroll
        for (int q = 0; q < 2; q++) {
            int idx = tid + q * 128;
            int off = (bbase + n0 + (idx >> 5)) * K_ + (idx & 31);
            int ev = eidx[off];
            smf[OFF_SVALID / 4 + idx] = (ev != -1) ? 1.0f : 0.0f;
            sIdx[idx] = (ev == -1) ? 0 : ev;
            smf[OFF_SDIST / 4 + idx] = dists[off];
        }
#pragma unroll
        for (int q = 0; q < 4; q++) {
            int idx = tid + q * 128;
            int s = idx >> 6, i = idx & 63;
            int row = bbase + n0 + s;
            smf[OFF_SSELF / 4 + idx] = emb[row * 64 + i] * mask[row];
            smf[OFF_SELFC / 4 + idx] = g_selfc[(size_t)(bbase + n0) * 64 + idx];
        }
        __syncthreads();

        // ---- phase 2: gather 256 src rows (fp16x2) + fact ----
#pragma unroll
        for (int q = 0; q < 32; q++) {
            int p = tid + q * 128;
            int row = p >> 4, c4 = p & 15;
            int gr = bbase + sIdx[row];
            float m = mask[gr];
            float4 v4 = reinterpret_cast<const float4*>(emb)[(size_t)gr * 16 + c4];
            uint2 pk;
            pk.x = pack_f16x2(v4.x * m, v4.y * m);
            pk.y = pack_f16x2(v4.z * m, v4.w * m);
            reinterpret_cast<uint2*>(smb + OFF_AGH)[row * 17 + c4] = pk;
        }
        if (tid < 8) {
            float c = 0.0f;
            for (int e = 0; e < 32; e++) c += smf[OFF_SVALID / 4 + tid * 32 + e];
            if (c == 0.0f) c = 1.0f;
            smf[OFF_FACT / 4 + tid] = mask[bbase + n0 + tid] * 0.5f / c;
        }
        __syncthreads();

        // ---- per-warp row metadata (warp w owns nodes 2w,2w+1: rows 64w..64w+63) ----
        float dr[8], vv[8];
#pragma unroll
        for (int j = 0; j < 8; j++) {
            dr[j] = smf[OFF_SDIST / 4 + w * 64 + 8 * j + lq];
            vv[j] = smf[OFF_SVALID / 4 + w * 64 + 8 * j + lq];
        }

        // ---- layer-0 A fragments: 4 m-tiles of 16 rows ----
        uint32_t ah[4][4][4];
        {
            const uint32_t* agh = reinterpret_cast<const uint32_t*>(smb + OFF_AGH);
#pragma unroll
            for (int mt = 0; mt < 4; mt++) {
                int rbase = w * 64 + mt * 16 + lq;
#pragma unroll
                for (int s = 0; s < 4; s++) {
                    int c2 = 8 * s + lr;
                    ah[mt][s][0] = agh[rbase * 34 + c2];
                    ah[mt][s][1] = agh[(rbase + 8) * 34 + c2];
                    ah[mt][s][2] = agh[rbase * 34 + c2 + 4];
                    ah[mt][s][3] = agh[(rbase + 8) * 34 + c2 + 4];
                }
            }
        }

        // ---- 3 layers, B fragments shared across 4 m-tiles ----
        float sc[2][16];
#pragma unroll
        for (int l = 0; l < 3; l++) {
            uint32_t ahn[4][4][4];
            if (l == 2) {
#pragma unroll
                for (int nd = 0; nd < 2; nd++)
#pragma unroll
                    for (int i = 0; i < 16; i++) sc[nd][i] = 0.0f;
            }
#pragma unroll
            for (int s = 0; s < 4; s++) {
#pragma unroll
                for (int half = 0; half < 2; half++) {
                    const int t = 2 * s + half;
                    const char* base = smb + OFF_BFRAG + (l * 8 + t) * 2048;
                    const uint4* bph = reinterpret_cast<const uint4*>(base + lane * 32);
                    uint4 h0 = bph[0], h1 = bph[1];
                    const uint4* bpl = reinterpret_cast<const uint4*>(base + 1024 + lane * 32);
                    uint4 L0 = bpl[0], L1 = bpl[1];
                    const int c0 = 8 * t + 2 * lr;
#pragma unroll
                    for (int mt = 0; mt < 4; mt++) {
                        const int nd = mt >> 1;               // node within warp
                        float dacc[4];
                        if (l == 0) {
                            float s0 = smf[OFF_SELFC / 4 + (2 * w + nd) * 64 + c0];
                            float s1 = smf[OFF_SELFC / 4 + (2 * w + nd) * 64 + c0 + 1];
                            float wd0 = smf[OFF_WD / 4 + c0];
                            float wd1 = smf[OFF_WD / 4 + c0 + 1];
                            dacc[0] = fmaf(dr[2 * mt], wd0, s0);
                            dacc[1] = fmaf(dr[2 * mt], wd1, s1);
                            dacc[2] = fmaf(dr[2 * mt + 1], wd0, s0);
                            dacc[3] = fmaf(dr[2 * mt + 1], wd1, s1);
                        } else {
                            const float* bb = smf + ((l == 1) ? OFF_B1S : OFF_B2S) / 4;
                            float b0v = bb[c0], b1v = bb[c0 + 1];
                            dacc[0] = b0v; dacc[1] = b1v;
                            dacc[2] = b0v; dacc[3] = b1v;
                        }
                        mma_f16(dacc, ah[mt][0][0], ah[mt][0][1], ah[mt][0][2], ah[mt][0][3], h0.x, h0.y);
                        mma_f16(dacc, ah[mt][1][0], ah[mt][1][1], ah[mt][1][2], ah[mt][1][3], h0.z, h0.w);
                        mma_f16(dacc, ah[mt][2][0], ah[mt][2][1], ah[mt][2][2], ah[mt][2][3], h1.x, h1.y);
                        mma_f16(dacc, ah[mt][3][0], ah[mt][3][1], ah[mt][3][2], ah[mt][3][3], h1.z, h1.w);
                        float tmp[4] = {0.0f, 0.0f, 0.0f, 0.0f};
                        mma_f16(tmp, ah[mt][0][0], ah[mt][0][1], ah[mt][0][2], ah[mt][0][3], L0.x, L0.y);
                        mma_f16(tmp, ah[mt][1][0], ah[mt][1][1], ah[mt][1][2], ah[mt][1][3], L0.z, L0.w);
                        mma_f16(tmp, ah[mt][2][0], ah[mt][2][1], ah[mt][2][2], ah[mt][2][3], L1.x, L1.y);
                        mma_f16(tmp, ah[mt][3][0], ah[mt][3][1], ah[mt][3][2], ah[mt][3][3], L1.z, L1.w);
#pragma unroll
                        for (int j = 0; j < 4; j++)
                            dacc[j] = fmaf(tmp[j], 0.00390625f, dacc[j]);   // 2^-8

                        ull g01 = gelu2x_pk(pk2(dacc[0], dacc[1]), K);
                        ull g23 = gelu2x_pk(pk2(dacc[2], dacc[3]), K);
                        if (l < 2) {
                            ahn[mt][s][2 * half]     = pk_to_f16(g01);
                            ahn[mt][s][2 * half + 1] = pk_to_f16(g23);
                        } else {
                            ull vp0 = pk2(vv[2 * mt], vv[2 * mt]);
                            ull vp1 = pk2(vv[2 * mt + 1], vv[2 * mt + 1]);
                            ull scp = f2fma(g01, vp0, f2mul(g23, vp1));
                            float a0, a1; upk2(scp, a0, a1);
                            sc[nd][2 * t]     += a0;
                            sc[nd][2 * t + 1] += a1;
                        }
                    }
                }
            }
            if (l < 2) {
#pragma unroll
                for (int mt = 0; mt < 4; mt++)
#pragma unroll
                    for (int s = 0; s < 4; s++)
#pragma unroll
                        for (int j = 0; j < 4; j++)
                            ah[mt][s][j] = ahn[mt][s][j];
            }
        }

        // ---- warp-level reduce for both owned nodes ----
#pragma unroll
        for (int off = 4; off <= 16; off <<= 1)
#pragma unroll
            for (int nd = 0; nd < 2; nd++)
#pragma unroll
                for (int i = 0; i < 16; i++)
                    sc[nd][i] += __shfl_xor_sync(0xFFFFFFFFu, sc[nd][i], off);
        if (lane < 4) {
#pragma unroll
            for (int nd = 0; nd < 2; nd++)
#pragma unroll
                for (int t = 0; t < 8; t++) {
                    smf[OFF_PART / 4 + (2 * w + nd) * 64 + 8 * t + 2 * lane]     = sc[nd][2 * t];
                    smf[OFF_PART / 4 + (2 * w + nd) * 64 + 8 * t + 2 * lane + 1] = sc[nd][2 * t + 1];
                }
        }
        __syncthreads();

        // ---- combine + write upd + stage stats (UPD aliases AGH) ----
#pragma unroll
        for (int q = 0; q < 4; q++) {
            int idx = tid + q * 128;
            int s = idx >> 6, d = idx & 63;
            float msg = smf[OFF_PART / 4 + s * 64 + d];
            float upd = smf[OFF_SSELF / 4 + idx] + msg * smf[OFF_FACT / 4 + s];
            g_upd[(size_t)(bbase + n0 + s) * 64 + d] = upd;
            smf[OFF_UPD / 4 + idx]       = upd;
            smf[OFF_UPD / 4 + 512 + idx] = upd * upd;
        }
        __syncthreads();
        if (tid < 64) {
            const float* st = smf + OFF_UPD / 4;
            float s1 = 0.0f, s2 = 0.0f;
#pragma unroll
            for (int k = 0; k < 8; k++) {
                s1 += st[k * 64 + tid];
                s2 += st[512 + k * 64 + tid];
            }
            smf[OFF_SACC / 4 + b * 128 + tid]      += s1;
            smf[OFF_SACC / 4 + b * 128 + 64 + tid] += s2;
        }
    }

    // ---- flush block-local stats ----
    __syncthreads();
    for (int p = tid; p < 1024; p += 128) {
        int bb2 = p >> 7;
        int rem = p & 127;
        float v = smf[OFF_SACC / 4 + p];
        if (rem < 64) atomicAdd(&g_sum[bb2][rem], v);
        else          atomicAdd(&g_sqs[bb2][rem - 64], v);
    }
}

// ---------------- selfC precompute: b0 + self-half of layer 0 ----------------
__global__ void __launch_bounds__(256)
selfc_kernel(const float* __restrict__ emb,
             const float* __restrict__ mask,
             const float* __restrict__ W0,
             const float* __restrict__ b0) {
    __shared__ float wsm[64 * 65];    // [i][d] stride 65
    __shared__ float sself[16 * 64];
    const int tid = threadIdx.x;
    for (int p = tid; p < 4096; p += 256) {
        int d = p >> 6, i = p & 63;
        wsm[i * 65 + d] = W0[d * 129 + 64 + i];
    }
    const int bn0 = blockIdx.x * 16;
#pragma unroll
    for (int q = 0; q < 4; q++) {
        int idx = tid + q * 256;
        int nl = idx >> 6, i = idx & 63;
        int bn = bn0 + nl;
        sself[idx] = emb[bn * 64 + i] * mask[bn];
    }
    __syncthreads();
    const int d = tid & 63;
#pragma unroll
    for (int nn = 0; nn < 4; nn++) {
        int nl = (tid >> 6) + nn * 4;
        float a = b0[d];
        const float* sv = sself + nl * 64;
#pragma unroll 8
        for (int i = 0; i < 64; i++) a = fmaf(sv[i], wsm[i * 65 + d], a);
        g_selfc[(size_t)(bn0 + nl) * 64 + d] = a;
    }
}

// ---------------- init: zero stats + mask counts ----------------
__global__ void __launch_bounds__(256)
init_stats_kernel(const float* __restrict__ mask) {
    __shared__ float sh[256];
    const int b = blockIdx.x;
    const int tid = threadIdx.x;
    if (tid < 64) {
        g_sum[b][tid] = 0.0f;
        g_sqs[b][tid] = 0.0f;
    }
    float c = 0.0f;
    for (int i = tid; i < N_; i += 256) c += mask[b * N_ + i];
    sh[tid] = c;
    __syncthreads();
    for (int st = 128; st >= 1; st >>= 1) {
        if (tid < st) sh[tid] += sh[tid + st];
        __syncthreads();
    }
    if (tid == 0) {
        float cc = sh[0];
        g_cnt[b] = (cc == 0.0f) ? 1.0f : cc;
    }
}

__global__ void __launch_bounds__(256)
norm_kernel(const float* __restrict__ mask,
            const float* __restrict__ scale,
            const float* __restrict__ shift,
            float* __restrict__ out) {
    int t = blockIdx.x * 256 + threadIdx.x;
    int bn = t >> 4;
    int b  = bn >> 13;
    int d0 = (t & 15) << 2;
    float cnt = g_cnt[b];
    float4 s1 = *reinterpret_cast<const float4*>(&g_sum[b][d0]);
    float4 s2 = *reinterpret_cast<const float4*>(&g_sqs[b][d0]);
    float4 u  = reinterpret_cast<const float4*>(g_upd)[t];
    float m   = mask[bn];
    float rc  = 1.0f / cnt;
    float4 o;
    {
        float mean = s1.x * rc;
        float var  = (s2.x - 2.0f * mean * s1.x + (float)N_ * mean * mean) * rc;
        o.x = fmaf((u.x - mean) * rsqrtf(var + 1e-5f), scale[d0 + 0], shift[d0 + 0]) * m;
    }
    {
        float mean = s1.y * rc;
        float var  = (s2.y - 2.0f * mean * s1.y + (float)N_ * mean * mean) * rc;
        o.y = fmaf((u.y - mean) * rsqrtf(var + 1e-5f), scale[d0 + 1], shift[d0 + 1]) * m;
    }
    {
        float mean = s1.z * rc;
        float var  = (s2.z - 2.0f * mean * s1.z + (float)N_ * mean * mean) * rc;
        o.z = fmaf((u.z - mean) * rsqrtf(var + 1e-5f), scale[d0 + 2], shift[d0 + 2]) * m;
    }
    {
        float mean = s1.w * rc;
        float var  = (s2.w - 2.0f * mean * s1.w + (float)N_ * mean * mean) * rc;
        o.w = fmaf((u.w - mean) * rsqrtf(var + 1e-5f), scale[d0 + 3], shift[d0 + 3]) * m;
    }
    reinterpret_cast<float4*>(out)[t] = o;
}

extern "C" void kernel_launch(void* const* d_in, const int* in_sizes, int n_in,
                              void* d_out, int out_size) {
    const float* emb   = (const float*)d_in[0];
    const float* dists = (const float*)d_in[1];
    const int*   eidx  = (const int*)d_in[2];
    const float* mask  = (const float*)d_in[3];
    const float* W0 = (const float*)d_in[4];
    const float* b0 = (const float*)d_in[5];
    const float* W1 = (const float*)d_in[6];
    const float* b1 = (const float*)d_in[7];
    const float* W2 = (const float*)d_in[8];
    const float* b2 = (const float*)d_in[9];
    const float* scale = (const float*)d_in[10];
    const float* shift = (const float*)d_in[11];
    float* out = (float*)d_out;

    int smc = 148;
    cudaDeviceGetAttribute(&smc, cudaDevAttrMultiProcessorCount, 0);

    cudaFuncSetAttribute(mpnn_msg_kernel,
                         cudaFuncAttributeMaxDynamicSharedMemorySize, SMEM_BYTES);

    init_stats_kernel<<<B_, 256>>>(mask);
    selfc_kernel<<<B_ * N_ / 16, 256>>>(emb, mask, W0, b0);
    mpnn_msg_kernel<<<2 * smc, 128, SMEM_BYTES>>>(emb, dists, eidx, mask,
                                                  W0, b0, W1, b1, W2, b2);
    norm_kernel<<<(B_ * N_ * D_ / 4 + 255) / 256, 256>>>(mask, scale, shift, out);
}

// round 12
// speedup vs baseline: 1.1064x; 1.1064x over previous
#include <cuda_runtime.h>
#include <cuda_fp16.h>
#include <math.h>
#include <cstdint>

#define B_ 8
#define N_ 8192
#define K_ 32
#define D_ 64

typedef unsigned long long ull;

// ---------------- dynamic smem byte offsets ----------------
#define OFF_BFRAG   0          // B frags: 24 combos x (hi 1024B + lo 1024B), lo scaled x256; W1,W2 pre-halved
#define OFF_AGH     49152      // 256 rows x 34 uint (fp16x2 gathered src), 34816B
#define OFF_SSELF   83968      // 8 x 64 f32 (emb*mask per node)
#define OFF_SELFC   86016      // 8 x 64 f32 (b0 + self-part of layer 0, precomputed)
#define OFF_SDIST   88064      // 256 f32
#define OFF_SVALID  89088      // 256 f32
#define OFF_SIDX    90112      // 256 i32
#define OFF_WD      91136      // 64 f32 (W0[:,128] dist column)
#define OFF_B1S     91392      // 64 f32
#define OFF_B2S     91648      // 64 f32
#define OFF_SACC    91904      // 8 b x 64 d x 2 f32 block-local stats accumulators
#define SMEM_BYTES  96256

// ---------------- device scratch ----------------
__device__ float g_upd[B_ * N_ * D_];
__device__ float g_selfc[B_ * N_ * D_];
__device__ float g_sum[B_][D_];
__device__ float g_sqs[B_][D_];
__device__ float g_cnt[B_];

// ---------------- packed f32x2 helpers ----------------
__device__ __forceinline__ ull pk2(float a, float b) {
    ull r; asm("mov.b64 %0, {%1, %2};" : "=l"(r) : "f"(a), "f"(b)); return r;
}
__device__ __forceinline__ void upk2(ull v, float& a, float& b) {
    asm("mov.b64 {%0, %1}, %2;" : "=f"(a), "=f"(b) : "l"(v));
}
__device__ __forceinline__ ull f2mul(ull a, ull b) {
    ull r; asm("mul.rn.f32x2 %0, %1, %2;" : "=l"(r) : "l"(a), "l"(b)); return r;
}
__device__ __forceinline__ ull f2fma(ull a, ull b, ull c) {
    ull r; asm("fma.rn.f32x2 %0, %1, %2, %3;" : "=l"(r) : "l"(a), "l"(b), "l"(c)); return r;
}

// packed gelu constants
struct GP { ull C1, C2; };

// packed 2*gelu(x): x * (1 + tanh(0.79788456*x + 0.03567741*x^3)), hw tanh
__device__ __forceinline__ ull gelu2x_pk(ull x, const GP& K) {
    ull xx = f2mul(x, x);
    ull c  = f2fma(xx, K.C2, K.C1);
    ull u  = f2mul(c, x);
    float u0, u1; upk2(u, u0, u1);
    float t0, t1;
    asm("tanh.approx.f32 %0, %1;" : "=f"(t0) : "f"(u0));
    asm("tanh.approx.f32 %0, %1;" : "=f"(t1) : "f"(u1));
    ull t = pk2(t0, t1);
    return f2fma(x, t, x);
}

__device__ __forceinline__ uint32_t pack_f16x2(float lo, float hi) {
    uint32_t r;
    asm("cvt.rn.f16x2.f32 %0, %1, %2;" : "=r"(r) : "f"(hi), "f"(lo));
    return r;
}
__device__ __forceinline__ uint32_t pk_to_f16(ull v) {
    float a, b; upk2(v, a, b);
    return pack_f16x2(a, b);
}

__device__ __forceinline__ void mma_f16(float* d,
                                        uint32_t a0, uint32_t a1, uint32_t a2, uint32_t a3,
                                        uint32_t b0, uint32_t b1) {
    asm volatile(
        "mma.sync.aligned.m16n8k16.row.col.f32.f16.f16.f32 "
        "{%0,%1,%2,%3}, {%4,%5,%6,%7}, {%8,%9}, {%0,%1,%2,%3};"
        : "+f"(d[0]), "+f"(d[1]), "+f"(d[2]), "+f"(d[3])
        : "r"(a0), "r"(a1), "r"(a2), "r"(a3), "r"(b0), "r"(b1));
}

__global__ void __launch_bounds__(256, 2)
mpnn_msg_kernel(const float* __restrict__ emb,
                const float* __restrict__ dists,
                const int*   __restrict__ eidx,
                const float* __restrict__ mask,
                const float* __restrict__ W0, const float* __restrict__ b0,
                const float* __restrict__ W1, const float* __restrict__ b1,
                const float* __restrict__ W2, const float* __restrict__ b2)
{
    extern __shared__ char smb[];
    float* smf = reinterpret_cast<float*>(smb);
    const int tid = threadIdx.x;
    const int w = tid >> 5, lane = tid & 31;
    const int lq = lane >> 2;      // 0..7 (row group)
    const int lr = lane & 3;       // 0..3 (col pair group)

    GP K;
    K.C1 = pk2(0.7978845608f, 0.7978845608f);
    K.C2 = pk2(0.03567740814f, 0.03567740814f);

    // ---- one-time staging: B fragments (fp16 hi + lo*256), wd, biases ----
    for (int c = w; c < 24; c += 8) {
        const int l = c >> 3, t = c & 7;
        const float* W = (l == 0) ? W0 : (l == 1) ? W1 : W2;
        const int stride = (l == 0) ? 129 : 64;
        const float wsc = (l == 0) ? 1.0f : 0.5f;
        const int n = t * 8 + lq;
        uint32_t hi[8], lo[8];
#pragma unroll
        for (int j = 0; j < 8; j++) {
            int s = j >> 1, rsel = j & 1;
            int k = 16 * s + 8 * rsel + 2 * lr;
            float x0 = W[n * stride + k] * wsc;
            float x1 = W[n * stride + k + 1] * wsc;
            uint32_t h = pack_f16x2(x0, x1);
            __half2 hh = *reinterpret_cast<__half2*>(&h);
            float r0f = x0 - __low2float(hh);
            float r1f = x1 - __high2float(hh);
            hi[j] = h;
            lo[j] = pack_f16x2(r0f * 256.0f, r1f * 256.0f);
        }
        uint4* dh = reinterpret_cast<uint4*>(smb + OFF_BFRAG + c * 2048 + lane * 32);
        uint4* dl = reinterpret_cast<uint4*>(smb + OFF_BFRAG + c * 2048 + 1024 + lane * 32);
        dh[0] = make_uint4(hi[0], hi[1], hi[2], hi[3]);
        dh[1] = make_uint4(hi[4], hi[5], hi[6], hi[7]);
        dl[0] = make_uint4(lo[0], lo[1], lo[2], lo[3]);
        dl[1] = make_uint4(lo[4], lo[5], lo[6], lo[7]);
    }
    if (tid < 64) {
        smf[OFF_WD / 4 + tid]  = W0[tid * 129 + 128];
        smf[OFF_B1S / 4 + tid] = b1[tid];
        smf[OFF_B2S / 4 + tid] = b2[tid];
    }
    for (int p = tid; p < 1024; p += 256) smf[OFF_SACC / 4 + p] = 0.0f;
    __syncthreads();

    int* sIdx = reinterpret_cast<int*>(smb + OFF_SIDX);
    const int totalTiles = (B_ * N_) / 8;   // 8 nodes x 32 edges = 256 rows/tile

    // per-lane stats accumulators (d = 2*lane, 2*lane+1 of this warp's nodes)
    int   cur_b = 0;
    float a1x = 0.0f, a1y = 0.0f, a2x = 0.0f, a2y = 0.0f;

    for (int tile = blockIdx.x; tile < totalTiles; tile += gridDim.x) {
        const int bn0 = tile << 3;
        const int b   = bn0 >> 13;
        const int n0  = bn0 & (N_ - 1);
        const int bbase = b * N_;

        __syncthreads();   // all warps done reading previous tile's smem

        // ---- stats flush on batch change (uniform across block) ----
        if (b != cur_b) {
            atomicAdd(&smf[OFF_SACC / 4 + cur_b * 128 + 2 * lane],      a1x);
            atomicAdd(&smf[OFF_SACC / 4 + cur_b * 128 + 2 * lane + 1],  a1y);
            atomicAdd(&smf[OFF_SACC / 4 + cur_b * 128 + 64 + 2 * lane], a2x);
            atomicAdd(&smf[OFF_SACC / 4 + cur_b * 128 + 65 + 2 * lane], a2y);
            a1x = a1y = a2x = a2y = 0.0f;
            cur_b = b;
        }

        // ---- phase 1: edge meta + self emb + precomputed selfC ----
        {
            int off = (bbase + n0 + (tid >> 5)) * K_ + (tid & 31);
            int idx = eidx[off];
            smf[OFF_SVALID / 4 + tid] = (idx != -1) ? 1.0f : 0.0f;
            sIdx[tid] = (idx == -1) ? 0 : idx;
            smf[OFF_SDIST / 4 + tid] = dists[off];
        }
#pragma unroll
        for (int q = 0; q < 2; q++) {
            int idx = tid + q * 256;
            int s = idx >> 6, i = idx & 63;
            int row = bbase + n0 + s;
            smf[OFF_SSELF / 4 + idx] = emb[row * 64 + i] * mask[row];
            smf[OFF_SELFC / 4 + idx] = g_selfc[(size_t)(bbase + n0) * 64 + idx];
        }
        __syncthreads();

        // ---- phase 2: gather 256 src rows (fp16x2) ----
#pragma unroll
        for (int q = 0; q < 16; q++) {
            int p = tid + q * 256;
            int row = p >> 4, c4 = p & 15;
            int gr = bbase + sIdx[row];
            float m = mask[gr];
            float4 v4 = reinterpret_cast<const float4*>(emb)[(size_t)gr * 16 + c4];
            uint2 pk;
            pk.x = pack_f16x2(v4.x * m, v4.y * m);
            pk.y = pack_f16x2(v4.z * m, v4.w * m);
            reinterpret_cast<uint2*>(smb + OFF_AGH)[row * 17 + c4] = pk;
        }
        __syncthreads();

        // ---- per-warp row metadata (warp w owns node w: rows 32w..32w+31) ----
        float dr[4], vv[4];
        {
            int rb = w * 32 + lq;
            dr[0] = smf[OFF_SDIST / 4 + rb];
            dr[1] = smf[OFF_SDIST / 4 + rb + 8];
            dr[2] = smf[OFF_SDIST / 4 + rb + 16];
            dr[3] = smf[OFF_SDIST / 4 + rb + 24];
            vv[0] = smf[OFF_SVALID / 4 + rb];
            vv[1] = smf[OFF_SVALID / 4 + rb + 8];
            vv[2] = smf[OFF_SVALID / 4 + rb + 16];
            vv[3] = smf[OFF_SVALID / 4 + rb + 24];
        }

        // ---- layer-0 A fragments: 2 m-tiles of 16 rows ----
        uint32_t ah[2][4][4];
        {
            const uint32_t* agh = reinterpret_cast<const uint32_t*>(smb + OFF_AGH);
#pragma unroll
            for (int mt = 0; mt < 2; mt++) {
                int rbase = w * 32 + mt * 16 + lq;
#pragma unroll
                for (int s = 0; s < 4; s++) {
                    int c2 = 8 * s + lr;
                    ah[mt][s][0] = agh[rbase * 34 + c2];
                    ah[mt][s][1] = agh[(rbase + 8) * 34 + c2];
                    ah[mt][s][2] = agh[rbase * 34 + c2 + 4];
                    ah[mt][s][3] = agh[(rbase + 8) * 34 + c2 + 4];
                }
            }
        }

        // ---- 3 layers, B fragments shared across both m-tiles ----
        float sc[16];
#pragma unroll
        for (int l = 0; l < 3; l++) {
            uint32_t ahn[2][4][4];
            if (l == 2) {
#pragma unroll
                for (int i = 0; i < 16; i++) sc[i] = 0.0f;
            }
#pragma unroll
            for (int s = 0; s < 4; s++) {
#pragma unroll
                for (int half = 0; half < 2; half++) {
                    const int t = 2 * s + half;
                    const char* base = smb + OFF_BFRAG + (l * 8 + t) * 2048;
                    const uint4* bph = reinterpret_cast<const uint4*>(base + lane * 32);
                    uint4 h0 = bph[0], h1 = bph[1];
                    const uint4* bpl = reinterpret_cast<const uint4*>(base + 1024 + lane * 32);
                    uint4 L0 = bpl[0], L1 = bpl[1];
                    const int c0 = 8 * t + 2 * lr;
#pragma unroll
                    for (int mt = 0; mt < 2; mt++) {
                        float dacc[4];
                        if (l == 0) {
                            float s0 = smf[OFF_SELFC / 4 + w * 64 + c0];
                            float s1 = smf[OFF_SELFC / 4 + w * 64 + c0 + 1];
                            float wd0 = smf[OFF_WD / 4 + c0];
                            float wd1 = smf[OFF_WD / 4 + c0 + 1];
                            dacc[0] = fmaf(dr[2 * mt], wd0, s0);
                            dacc[1] = fmaf(dr[2 * mt], wd1, s1);
                            dacc[2] = fmaf(dr[2 * mt + 1], wd0, s0);
                            dacc[3] = fmaf(dr[2 * mt + 1], wd1, s1);
                        } else {
                            const float* bb = smf + ((l == 1) ? OFF_B1S : OFF_B2S) / 4;
                            float b0v = bb[c0], b1v = bb[c0 + 1];
                            dacc[0] = b0v; dacc[1] = b1v;
                            dacc[2] = b0v; dacc[3] = b1v;
                        }
                        mma_f16(dacc, ah[mt][0][0], ah[mt][0][1], ah[mt][0][2], ah[mt][0][3], h0.x, h0.y);
                        mma_f16(dacc, ah[mt][1][0], ah[mt][1][1], ah[mt][1][2], ah[mt][1][3], h0.z, h0.w);
                        mma_f16(dacc, ah[mt][2][0], ah[mt][2][1], ah[mt][2][2], ah[mt][2][3], h1.x, h1.y);
                        mma_f16(dacc, ah[mt][3][0], ah[mt][3][1], ah[mt][3][2], ah[mt][3][3], h1.z, h1.w);
                        float tmp[4] = {0.0f, 0.0f, 0.0f, 0.0f};
                        mma_f16(tmp, ah[mt][0][0], ah[mt][0][1], ah[mt][0][2], ah[mt][0][3], L0.x, L0.y);
                        mma_f16(tmp, ah[mt][1][0], ah[mt][1][1], ah[mt][1][2], ah[mt][1][3], L0.z, L0.w);
                        mma_f16(tmp, ah[mt][2][0], ah[mt][2][1], ah[mt][2][2], ah[mt][2][3], L1.x, L1.y);
                        mma_f16(tmp, ah[mt][3][0], ah[mt][3][1], ah[mt][3][2], ah[mt][3][3], L1.z, L1.w);
#pragma unroll
                        for (int j = 0; j < 4; j++)
                            dacc[j] = fmaf(tmp[j], 0.00390625f, dacc[j]);   // 2^-8

                        ull g01 = gelu2x_pk(pk2(dacc[0], dacc[1]), K);
                        ull g23 = gelu2x_pk(pk2(dacc[2], dacc[3]), K);
                        if (l < 2) {
                            ahn[mt][s][2 * half]     = pk_to_f16(g01);
                            ahn[mt][s][2 * half + 1] = pk_to_f16(g23);
                        } else {
                            ull vp0 = pk2(vv[2 * mt], vv[2 * mt]);
                            ull vp1 = pk2(vv[2 * mt + 1], vv[2 * mt + 1]);
                            ull scp = f2fma(g01, vp0, f2mul(g23, vp1));
                            float a0, a1; upk2(scp, a0, a1);
                            sc[2 * t]     += a0;
                            sc[2 * t + 1] += a1;
                        }
                    }
                }
            }
            if (l < 2) {
#pragma unroll
                for (int mt = 0; mt < 2; mt++)
#pragma unroll
                    for (int s = 0; s < 4; s++)
#pragma unroll
                        for (int j = 0; j < 4; j++)
                            ah[mt][s][j] = ahn[mt][s][j];
            }
        }

        // ---- warp-local reduce + direct epilogue (no block sync) ----
        float nv = vv[0] + vv[1] + vv[2] + vv[3];
#pragma unroll
        for (int off = 4; off <= 16; off <<= 1) {
            nv += __shfl_xor_sync(0xFFFFFFFFu, nv, off);
#pragma unroll
            for (int i = 0; i < 16; i++)
                sc[i] += __shfl_xor_sync(0xFFFFFFFFu, sc[i], off);
        }
        {
            if (nv == 0.0f) nv = 1.0f;
            float fact = mask[bbase + n0 + w] * 0.5f / nv;
            int t = lane >> 2;
            float u0 = fmaf(sc[2 * t],     fact, smf[OFF_SSELF / 4 + w * 64 + 2 * lane]);
            float u1 = fmaf(sc[2 * t + 1], fact, smf[OFF_SSELF / 4 + w * 64 + 2 * lane + 1]);
            float2 uo; uo.x = u0; uo.y = u1;
            *reinterpret_cast<float2*>(&g_upd[(size_t)(bbase + n0 + w) * 64 + 2 * lane]) = uo;
            a1x += u0;
            a1y += u1;
            a2x = fmaf(u0, u0, a2x);
            a2y = fmaf(u1, u1, a2y);
        }
    }

    // ---- final register flush + global flush ----
    atomicAdd(&smf[OFF_SACC / 4 + cur_b * 128 + 2 * lane],      a1x);
    atomicAdd(&smf[OFF_SACC / 4 + cur_b * 128 + 2 * lane + 1],  a1y);
    atomicAdd(&smf[OFF_SACC / 4 + cur_b * 128 + 64 + 2 * lane], a2x);
    atomicAdd(&smf[OFF_SACC / 4 + cur_b * 128 + 65 + 2 * lane], a2y);
    __syncthreads();
    for (int p = tid; p < 1024; p += 256) {
        int bb2 = p >> 7;
        int rem = p & 127;
        float v = smf[OFF_SACC / 4 + p];
        if (rem < 64) atomicAdd(&g_sum[bb2][rem], v);
        else          atomicAdd(&g_sqs[bb2][rem - 64], v);
    }
}

// ---------------- selfC precompute: b0 + self-half of layer 0 ----------------
__global__ void __launch_bounds__(256)
selfc_kernel(const float* __restrict__ emb,
             const float* __restrict__ mask,
             const float* __restrict__ W0,
             const float* __restrict__ b0) {
    __shared__ float wsm[64 * 65];    // [i][d] stride 65
    __shared__ float sself[16 * 64];
    const int tid = threadIdx.x;
    for (int p = tid; p < 4096; p += 256) {
        int d = p >> 6, i = p & 63;
        wsm[i * 65 + d] = W0[d * 129 + 64 + i];
    }
    const int bn0 = blockIdx.x * 16;
#pragma unroll
    for (int q = 0; q < 4; q++) {
        int idx = tid + q * 256;
        int nl = idx >> 6, i = idx & 63;
        int bn = bn0 + nl;
        sself[idx] = emb[bn * 64 + i] * mask[bn];
    }
    __syncthreads();
    const int d = tid & 63;
#pragma unroll
    for (int nn = 0; nn < 4; nn++) {
        int nl = (tid >> 6) + nn * 4;
        float a = b0[d];
        const float* sv = sself + nl * 64;
#pragma unroll 8
        for (int i = 0; i < 64; i++) a = fmaf(sv[i], wsm[i * 65 + d], a);
        g_selfc[(size_t)(bn0 + nl) * 64 + d] = a;
    }
}

// ---------------- init: zero stats + mask counts ----------------
__global__ void __launch_bounds__(256)
init_stats_kernel(const float* __restrict__ mask) {
    __shared__ float sh[256];
    const int b = blockIdx.x;
    const int tid = threadIdx.x;
    if (tid < 64) {
        g_sum[b][tid] = 0.0f;
        g_sqs[b][tid] = 0.0f;
    }
    float c = 0.0f;
    for (int i = tid; i < N_; i += 256) c += mask[b * N_ + i];
    sh[tid] = c;
    __syncthreads();
    for (int st = 128; st >= 1; st >>= 1) {
        if (tid < st) sh[tid] += sh[tid + st];
        __syncthreads();
    }
    if (tid == 0) {
        float cc = sh[0];
        g_cnt[b] = (cc == 0.0f) ? 1.0f : cc;
    }
}

__global__ void __launch_bounds__(256)
norm_kernel(const float* __restrict__ mask,
            const float* __restrict__ scale,
            const float* __restrict__ shift,
            float* __restrict__ out) {
    int t = blockIdx.x * 256 + threadIdx.x;
    int bn = t >> 4;
    int b  = bn >> 13;
    int d0 = (t & 15) << 2;
    float cnt = g_cnt[b];
    float4 s1 = *reinterpret_cast<const float4*>(&g_sum[b][d0]);
    float4 s2 = *reinterpret_cast<const float4*>(&g_sqs[b][d0]);
    float4 u  = reinterpret_cast<const float4*>(g_upd)[t];
    float m   = mask[bn];
    float rc  = 1.0f / cnt;
    float4 o;
    {
        float mean = s1.x * rc;
        float var  = (s2.x - 2.0f * mean * s1.x + (float)N_ * mean * mean) * rc;
        o.x = fmaf((u.x - mean) * rsqrtf(var + 1e-5f), scale[d0 + 0], shift[d0 + 0]) * m;
    }
    {
        float mean = s1.y * rc;
        float var  = (s2.y - 2.0f * mean * s1.y + (float)N_ * mean * mean) * rc;
        o.y = fmaf((u.y - mean) * rsqrtf(var + 1e-5f), scale[d0 + 1], shift[d0 + 1]) * m;
    }
    {
        float mean = s1.z * rc;
        float var  = (s2.z - 2.0f * mean * s1.z + (float)N_ * mean * mean) * rc;
        o.z = fmaf((u.z - mean) * rsqrtf(var + 1e-5f), scale[d0 + 2], shift[d0 + 2]) * m;
    }
    {
        float mean = s1.w * rc;
        float var  = (s2.w - 2.0f * mean * s1.w + (float)N_ * mean * mean) * rc;
        o.w = fmaf((u.w - mean) * rsqrtf(var + 1e-5f), scale[d0 + 3], shift[d0 + 3]) * m;
    }
    reinterpret_cast<float4*>(out)[t] = o;
}

extern "C" void kernel_launch(void* const* d_in, const int* in_sizes, int n_in,
                              void* d_out, int out_size) {
    const float* emb   = (const float*)d_in[0];
    const float* dists = (const float*)d_in[1];
    const int*   eidx  = (const int*)d_in[2];
    const float* mask  = (const float*)d_in[3];
    const float* W0 = (const float*)d_in[4];
    const float* b0 = (const float*)d_in[5];
    const float* W1 = (const float*)d_in[6];
    const float* b1 = (const float*)d_in[7];
    const float* W2 = (const float*)d_in[8];
    const float* b2 = (const float*)d_in[9];
    const float* scale = (const float*)d_in[10];
    const float* shift = (const float*)d_in[11];
    float* out = (float*)d_out;

    int smc = 148;
    cudaDeviceGetAttribute(&smc, cudaDevAttrMultiProcessorCount, 0);

    cudaFuncSetAttribute(mpnn_msg_kernel,
                         cudaFuncAttributeMaxDynamicSharedMemorySize, SMEM_BYTES);

    init_stats_kernel<<<B_, 256>>>(mask);
    selfc_kernel<<<B_ * N_ / 16, 256>>>(emb, mask, W0, b0);
    mpnn_msg_kernel<<<2 * smc, 256, SMEM_BYTES>>>(emb, dists, eidx, mask,
                                                  W0, b0, W1, b1, W2, b2);
    norm_kernel<<<(B_ * N_ * D_ / 4 + 255) / 256, 256>>>(mask, scale, shift, out);
}

// round 13
// speedup vs baseline: 1.2196x; 1.1023x over previous
#include <cuda_runtime.h>
#include <cuda_fp16.h>
#include <math.h>
#include <cstdint>

#define B_ 8
#define N_ 8192
#define K_ 32
#define D_ 64

typedef unsigned long long ull;

// ---------------- dynamic smem byte offsets ----------------
#define OFF_BFRAG   0          // B frags: 24 combos x (hi 1024B + lo 1024B), lo scaled x256; W1,W2 pre-halved
#define OFF_AGH     49152      // 256 rows x 36 uint (fp16x2 gathered src, uint4-padded), 36864B
#define OFF_SELFC   86016      // 8 x 64 f32 (b0 + self-part of layer 0, precomputed)
#define OFF_WD      88064      // 64 f32 (W0[:,128] dist column)
#define OFF_B1S     88320      // 64 f32
#define OFF_B2S     88576      // 64 f32
#define OFF_SACC    88832      // 8 b x 64 d x 2 f32 block-local stats accumulators
#define SMEM_BYTES  93184

// ---------------- device scratch ----------------
__device__ float g_upd[B_ * N_ * D_];
__device__ float g_selfc[B_ * N_ * D_];
__device__ unsigned int g_embh[B_ * N_ * 32];   // fp16x2(emb*mask), 32 uints/row
__device__ float g_sum[B_][D_];
__device__ float g_sqs[B_][D_];
__device__ float g_cnt[B_];

// ---------------- packed f32x2 helpers ----------------
__device__ __forceinline__ ull pk2(float a, float b) {
    ull r; asm("mov.b64 %0, {%1, %2};" : "=l"(r) : "f"(a), "f"(b)); return r;
}
__device__ __forceinline__ void upk2(ull v, float& a, float& b) {
    asm("mov.b64 {%0, %1}, %2;" : "=f"(a), "=f"(b) : "l"(v));
}
__device__ __forceinline__ ull f2mul(ull a, ull b) {
    ull r; asm("mul.rn.f32x2 %0, %1, %2;" : "=l"(r) : "l"(a), "l"(b)); return r;
}
__device__ __forceinline__ ull f2fma(ull a, ull b, ull c) {
    ull r; asm("fma.rn.f32x2 %0, %1, %2, %3;" : "=l"(r) : "l"(a), "l"(b), "l"(c)); return r;
}

// packed gelu constants
struct GP { ull C1, C2; };

// packed 2*gelu(x): x * (1 + tanh(0.79788456*x + 0.03567741*x^3)), hw tanh
__device__ __forceinline__ ull gelu2x_pk(ull x, const GP& K) {
    ull xx = f2mul(x, x);
    ull c  = f2fma(xx, K.C2, K.C1);
    ull u  = f2mul(c, x);
    float u0, u1; upk2(u, u0, u1);
    float t0, t1;
    asm("tanh.approx.f32 %0, %1;" : "=f"(t0) : "f"(u0));
    asm("tanh.approx.f32 %0, %1;" : "=f"(t1) : "f"(u1));
    ull t = pk2(t0, t1);
    return f2fma(x, t, x);
}

__device__ __forceinline__ uint32_t pack_f16x2(float lo, float hi) {
    uint32_t r;
    asm("cvt.rn.f16x2.f32 %0, %1, %2;" : "=r"(r) : "f"(hi), "f"(lo));
    return r;
}
__device__ __forceinline__ uint32_t pk_to_f16(ull v) {
    float a, b; upk2(v, a, b);
    return pack_f16x2(a, b);
}

__device__ __forceinline__ void mma_f16(float* d,
                                        uint32_t a0, uint32_t a1, uint32_t a2, uint32_t a3,
                                        uint32_t b0, uint32_t b1) {
    asm volatile(
        "mma.sync.aligned.m16n8k16.row.col.f32.f16.f16.f32 "
        "{%0,%1,%2,%3}, {%4,%5,%6,%7}, {%8,%9}, {%0,%1,%2,%3};"
        : "+f"(d[0]), "+f"(d[1]), "+f"(d[2]), "+f"(d[3])
        : "r"(a0), "r"(a1), "r"(a2), "r"(a3), "r"(b0), "r"(b1));
}

__global__ void __launch_bounds__(256, 2)
mpnn_msg_kernel(const float* __restrict__ emb,
                const float* __restrict__ dists,
                const int*   __restrict__ eidx,
                const float* __restrict__ mask,
                const float* __restrict__ W0, const float* __restrict__ b0,
                const float* __restrict__ W1, const float* __restrict__ b1,
                const float* __restrict__ W2, const float* __restrict__ b2)
{
    extern __shared__ char smb[];
    float* smf = reinterpret_cast<float*>(smb);
    const int tid = threadIdx.x;
    const int w = tid >> 5, lane = tid & 31;
    const int lq = lane >> 2;      // 0..7 (row group)
    const int lr = lane & 3;       // 0..3 (col pair group)

    GP K;
    K.C1 = pk2(0.7978845608f, 0.7978845608f);
    K.C2 = pk2(0.03567740814f, 0.03567740814f);

    // ---- one-time staging: B fragments (fp16 hi + lo*256), wd, biases ----
    for (int c = w; c < 24; c += 8) {
        const int l = c >> 3, t = c & 7;
        const float* W = (l == 0) ? W0 : (l == 1) ? W1 : W2;
        const int stride = (l == 0) ? 129 : 64;
        const float wsc = (l == 0) ? 1.0f : 0.5f;
        const int n = t * 8 + lq;
        uint32_t hi[8], lo[8];
#pragma unroll
        for (int j = 0; j < 8; j++) {
            int s = j >> 1, rsel = j & 1;
            int k = 16 * s + 8 * rsel + 2 * lr;
            float x0 = W[n * stride + k] * wsc;
            float x1 = W[n * stride + k + 1] * wsc;
            uint32_t h = pack_f16x2(x0, x1);
            __half2 hh = *reinterpret_cast<__half2*>(&h);
            float r0f = x0 - __low2float(hh);
            float r1f = x1 - __high2float(hh);
            hi[j] = h;
            lo[j] = pack_f16x2(r0f * 256.0f, r1f * 256.0f);
        }
        uint4* dh = reinterpret_cast<uint4*>(smb + OFF_BFRAG + c * 2048 + lane * 32);
        uint4* dl = reinterpret_cast<uint4*>(smb + OFF_BFRAG + c * 2048 + 1024 + lane * 32);
        dh[0] = make_uint4(hi[0], hi[1], hi[2], hi[3]);
        dh[1] = make_uint4(hi[4], hi[5], hi[6], hi[7]);
        dl[0] = make_uint4(lo[0], lo[1], lo[2], lo[3]);
        dl[1] = make_uint4(lo[4], lo[5], lo[6], lo[7]);
    }
    if (tid < 64) {
        smf[OFF_WD / 4 + tid]  = W0[tid * 129 + 128];
        smf[OFF_B1S / 4 + tid] = b1[tid];
        smf[OFF_B2S / 4 + tid] = b2[tid];
    }
    for (int p = tid; p < 1024; p += 256) smf[OFF_SACC / 4 + p] = 0.0f;
    __syncthreads();

    const int totalTiles = (B_ * N_) / 8;   // 8 nodes x 32 edges = 256 rows/tile

    // per-lane stats accumulators (d = 2*lane, 2*lane+1 of this warp's nodes)
    int   cur_b = 0;
    float a1x = 0.0f, a1y = 0.0f, a2x = 0.0f, a2y = 0.0f;

    for (int tile = blockIdx.x; tile < totalTiles; tile += gridDim.x) {
        const int bn0 = tile << 3;
        const int b   = bn0 >> 13;
        const int n0  = bn0 & (N_ - 1);
        const int bbase = b * N_;
        const int ebase = (bbase + n0) * K_;    // flat edge base for this tile

        __syncthreads();   // protect AGH/SELFC reuse across tiles

        // ---- stats flush on batch change (uniform across block) ----
        if (b != cur_b) {
            atomicAdd(&smf[OFF_SACC / 4 + cur_b * 128 + 2 * lane],      a1x);
            atomicAdd(&smf[OFF_SACC / 4 + cur_b * 128 + 2 * lane + 1],  a1y);
            atomicAdd(&smf[OFF_SACC / 4 + cur_b * 128 + 64 + 2 * lane], a2x);
            atomicAdd(&smf[OFF_SACC / 4 + cur_b * 128 + 65 + 2 * lane], a2y);
            a1x = a1y = a2x = a2y = 0.0f;
            cur_b = b;
        }

        // ---- gather: 256 rows x 32 uint (fp16x2) straight from g_embh ----
        {
            const uint4* embh4 = reinterpret_cast<const uint4*>(g_embh);
            uint4* agh4 = reinterpret_cast<uint4*>(smb + OFF_AGH);
#pragma unroll
            for (int q = 0; q < 8; q++) {
                int p = tid + q * 256;
                int row = p >> 3, c = p & 7;
                int ev = eidx[ebase + row];                 // L1 broadcast (8 thr/row)
                int gr = bbase + ((ev == -1) ? 0 : ev);
                agh4[row * 9 + c] = embh4[(size_t)gr * 8 + c];
            }
            // selfC into smem
#pragma unroll
            for (int q = 0; q < 2; q++) {
                int idx = tid + q * 256;
                smf[OFF_SELFC / 4 + idx] = g_selfc[(size_t)(bbase + n0) * 64 + idx];
            }
        }
        __syncthreads();

        // ---- per-warp row metadata straight from global (warp w = node w) ----
        float dr[4], vv[4];
#pragma unroll
        for (int j = 0; j < 4; j++) {
            int e = ebase + w * 32 + 8 * j + lq;
            dr[j] = dists[e];
            vv[j] = (eidx[e] != -1) ? 1.0f : 0.0f;
        }

        // ---- layer-0 A fragments: 2 m-tiles of 16 rows ----
        uint32_t ah[2][4][4];
        {
            const uint32_t* agh = reinterpret_cast<const uint32_t*>(smb + OFF_AGH);
#pragma unroll
            for (int mt = 0; mt < 2; mt++) {
                int rbase = w * 32 + mt * 16 + lq;
#pragma unroll
                for (int s = 0; s < 4; s++) {
                    int c2 = 8 * s + lr;
                    ah[mt][s][0] = agh[rbase * 36 + c2];
                    ah[mt][s][1] = agh[(rbase + 8) * 36 + c2];
                    ah[mt][s][2] = agh[rbase * 36 + c2 + 4];
                    ah[mt][s][3] = agh[(rbase + 8) * 36 + c2 + 4];
                }
            }
        }

        // ---- 3 layers, B fragments shared across both m-tiles ----
        float sc[16];
#pragma unroll
        for (int l = 0; l < 3; l++) {
            uint32_t ahn[2][4][4];
            if (l == 2) {
#pragma unroll
                for (int i = 0; i < 16; i++) sc[i] = 0.0f;
            }
#pragma unroll
            for (int s = 0; s < 4; s++) {
#pragma unroll
                for (int half = 0; half < 2; half++) {
                    const int t = 2 * s + half;
                    const char* base = smb + OFF_BFRAG + (l * 8 + t) * 2048;
                    const uint4* bph = reinterpret_cast<const uint4*>(base + lane * 32);
                    uint4 h0 = bph[0], h1 = bph[1];
                    const uint4* bpl = reinterpret_cast<const uint4*>(base + 1024 + lane * 32);
                    uint4 L0 = bpl[0], L1 = bpl[1];
                    const int c0 = 8 * t + 2 * lr;
#pragma unroll
                    for (int mt = 0; mt < 2; mt++) {
                        float dacc[4];
                        if (l == 0) {
                            float s0 = smf[OFF_SELFC / 4 + w * 64 + c0];
                            float s1 = smf[OFF_SELFC / 4 + w * 64 + c0 + 1];
                            float wd0 = smf[OFF_WD / 4 + c0];
                            float wd1 = smf[OFF_WD / 4 + c0 + 1];
                            dacc[0] = fmaf(dr[2 * mt], wd0, s0);
                            dacc[1] = fmaf(dr[2 * mt], wd1, s1);
                            dacc[2] = fmaf(dr[2 * mt + 1], wd0, s0);
                            dacc[3] = fmaf(dr[2 * mt + 1], wd1, s1);
                        } else {
                            const float* bb = smf + ((l == 1) ? OFF_B1S : OFF_B2S) / 4;
                            float b0v = bb[c0], b1v = bb[c0 + 1];
                            dacc[0] = b0v; dacc[1] = b1v;
                            dacc[2] = b0v; dacc[3] = b1v;
                        }
                        mma_f16(dacc, ah[mt][0][0], ah[mt][0][1], ah[mt][0][2], ah[mt][0][3], h0.x, h0.y);
                        mma_f16(dacc, ah[mt][1][0], ah[mt][1][1], ah[mt][1][2], ah[mt][1][3], h0.z, h0.w);
                        mma_f16(dacc, ah[mt][2][0], ah[mt][2][1], ah[mt][2][2], ah[mt][2][3], h1.x, h1.y);
                        mma_f16(dacc, ah[mt][3][0], ah[mt][3][1], ah[mt][3][2], ah[mt][3][3], h1.z, h1.w);
                        float tmp[4] = {0.0f, 0.0f, 0.0f, 0.0f};
                        mma_f16(tmp, ah[mt][0][0], ah[mt][0][1], ah[mt][0][2], ah[mt][0][3], L0.x, L0.y);
                        mma_f16(tmp, ah[mt][1][0], ah[mt][1][1], ah[mt][1][2], ah[mt][1][3], L0.z, L0.w);
                        mma_f16(tmp, ah[mt][2][0], ah[mt][2][1], ah[mt][2][2], ah[mt][2][3], L1.x, L1.y);
                        mma_f16(tmp, ah[mt][3][0], ah[mt][3][1], ah[mt][3][2], ah[mt][3][3], L1.z, L1.w);
#pragma unroll
                        for (int j = 0; j < 4; j++)
                            dacc[j] = fmaf(tmp[j], 0.00390625f, dacc[j]);   // 2^-8

                        ull g01 = gelu2x_pk(pk2(dacc[0], dacc[1]), K);
                        ull g23 = gelu2x_pk(pk2(dacc[2], dacc[3]), K);
                        if (l < 2) {
                            ahn[mt][s][2 * half]     = pk_to_f16(g01);
                            ahn[mt][s][2 * half + 1] = pk_to_f16(g23);
                        } else {
                            ull vp0 = pk2(vv[2 * mt], vv[2 * mt]);
                            ull vp1 = pk2(vv[2 * mt + 1], vv[2 * mt + 1]);
                            ull scp = f2fma(g01, vp0, f2mul(g23, vp1));
                            float a0, a1; upk2(scp, a0, a1);
                            sc[2 * t]     += a0;
                            sc[2 * t + 1] += a1;
                        }
                    }
                }
            }
            if (l < 2) {
#pragma unroll
                for (int mt = 0; mt < 2; mt++)
#pragma unroll
                    for (int s = 0; s < 4; s++)
#pragma unroll
                        for (int j = 0; j < 4; j++)
                            ah[mt][s][j] = ahn[mt][s][j];
            }
        }

        // ---- warp-local reduce + direct epilogue ----
        float nv = vv[0] + vv[1] + vv[2] + vv[3];
#pragma unroll
        for (int off = 4; off <= 16; off <<= 1) {
            nv += __shfl_xor_sync(0xFFFFFFFFu, nv, off);
#pragma unroll
            for (int i = 0; i < 16; i++)
                sc[i] += __shfl_xor_sync(0xFFFFFFFFu, sc[i], off);
        }
        {
            if (nv == 0.0f) nv = 1.0f;
            int row = bbase + n0 + w;
            float mk = mask[row];
            float fact = mk * 0.5f / nv;
            int t = lane >> 2;
            float2 se = *reinterpret_cast<const float2*>(&emb[(size_t)row * 64 + 2 * lane]);
            float u0 = fmaf(sc[2 * t],     fact, se.x * mk);
            float u1 = fmaf(sc[2 * t + 1], fact, se.y * mk);
            float2 uo; uo.x = u0; uo.y = u1;
            *reinterpret_cast<float2*>(&g_upd[(size_t)row * 64 + 2 * lane]) = uo;
            a1x += u0;
            a1y += u1;
            a2x = fmaf(u0, u0, a2x);
            a2y = fmaf(u1, u1, a2y);
        }
    }

    // ---- final register flush + global flush ----
    atomicAdd(&smf[OFF_SACC / 4 + cur_b * 128 + 2 * lane],      a1x);
    atomicAdd(&smf[OFF_SACC / 4 + cur_b * 128 + 2 * lane + 1],  a1y);
    atomicAdd(&smf[OFF_SACC / 4 + cur_b * 128 + 64 + 2 * lane], a2x);
    atomicAdd(&smf[OFF_SACC / 4 + cur_b * 128 + 65 + 2 * lane], a2y);
    __syncthreads();
    for (int p = tid; p < 1024; p += 256) {
        int bb2 = p >> 7;
        int rem = p & 127;
        float v = smf[OFF_SACC / 4 + p];
        if (rem < 64) atomicAdd(&g_sum[bb2][rem], v);
        else          atomicAdd(&g_sqs[bb2][rem - 64], v);
    }
}

// ---------------- emb -> fp16x2(emb*mask) pre-pass ----------------
__global__ void __launch_bounds__(256)
embh_kernel(const float* __restrict__ emb, const float* __restrict__ mask) {
    int t = blockIdx.x * 256 + threadIdx.x;     // B*N*16 threads, 4 floats each
    int row = t >> 4, c4 = t & 15;
    float m = mask[row];
    float4 v = reinterpret_cast<const float4*>(emb)[t];
    uint2 pk;
    pk.x = pack_f16x2(v.x * m, v.y * m);
    pk.y = pack_f16x2(v.z * m, v.w * m);
    reinterpret_cast<uint2*>(g_embh)[t] = pk;
}

// ---------------- selfC precompute: b0 + self-half of layer 0 ----------------
__global__ void __launch_bounds__(256)
selfc_kernel(const float* __restrict__ emb,
             const float* __restrict__ mask,
             const float* __restrict__ W0,
             const float* __restrict__ b0) {
    __shared__ float wsm[64 * 65];    // [i][d] stride 65
    __shared__ float sself[16 * 64];
    const int tid = threadIdx.x;
    for (int p = tid; p < 4096; p += 256) {
        int d = p >> 6, i = p & 63;
        wsm[i * 65 + d] = W0[d * 129 + 64 + i];
    }
    const int bn0 = blockIdx.x * 16;
#pragma unroll
    for (int q = 0; q < 4; q++) {
        int idx = tid + q * 256;
        int nl = idx >> 6, i = idx & 63;
        int bn = bn0 + nl;
        sself[idx] = emb[bn * 64 + i] * mask[bn];
    }
    __syncthreads();
    const int d = tid & 63;
#pragma unroll
    for (int nn = 0; nn < 4; nn++) {
        int nl = (tid >> 6) + nn * 4;
        float a = b0[d];
        const float* sv = sself + nl * 64;
#pragma unroll 8
        for (int i = 0; i < 64; i++) a = fmaf(sv[i], wsm[i * 65 + d], a);
        g_selfc[(size_t)(bn0 + nl) * 64 + d] = a;
    }
}

// ---------------- init: zero stats + mask counts ----------------
__global__ void __launch_bounds__(256)
init_stats_kernel(const float* __restrict__ mask) {
    __shared__ float sh[256];
    const int b = blockIdx.x;
    const int tid = threadIdx.x;
    if (tid < 64) {
        g_sum[b][tid] = 0.0f;
        g_sqs[b][tid] = 0.0f;
    }
    float c = 0.0f;
    for (int i = tid; i < N_; i += 256) c += mask[b * N_ + i];
    sh[tid] = c;
    __syncthreads();
    for (int st = 128; st >= 1; st >>= 1) {
        if (tid < st) sh[tid] += sh[tid + st];
        __syncthreads();
    }
    if (tid == 0) {
        float cc = sh[0];
        g_cnt[b] = (cc == 0.0f) ? 1.0f : cc;
    }
}

__global__ void __launch_bounds__(256)
norm_kernel(const float* __restrict__ mask,
            const float* __restrict__ scale,
            const float* __restrict__ shift,
            float* __restrict__ out) {
    int t = blockIdx.x * 256 + threadIdx.x;
    int bn = t >> 4;
    int b  = bn >> 13;
    int d0 = (t & 15) << 2;
    float cnt = g_cnt[b];
    float4 s1 = *reinterpret_cast<const float4*>(&g_sum[b][d0]);
    float4 s2 = *reinterpret_cast<const float4*>(&g_sqs[b][d0]);
    float4 u  = reinterpret_cast<const float4*>(g_upd)[t];
    float m   = mask[bn];
    float rc  = 1.0f / cnt;
    float4 o;
    {
        float mean = s1.x * rc;
        float var  = (s2.x - 2.0f * mean * s1.x + (float)N_ * mean * mean) * rc;
        o.x = fmaf((u.x - mean) * rsqrtf(var + 1e-5f), scale[d0 + 0], shift[d0 + 0]) * m;
    }
    {
        float mean = s1.y * rc;
        float var  = (s2.y - 2.0f * mean * s1.y + (float)N_ * mean * mean) * rc;
        o.y = fmaf((u.y - mean) * rsqrtf(var + 1e-5f), scale[d0 + 1], shift[d0 + 1]) * m;
    }
    {
        float mean = s1.z * rc;
        float var  = (s2.z - 2.0f * mean * s1.z + (float)N_ * mean * mean) * rc;
        o.z = fmaf((u.z - mean) * rsqrtf(var + 1e-5f), scale[d0 + 2], shift[d0 + 2]) * m;
    }
    {
        float mean = s1.w * rc;
        float var  = (s2.w - 2.0f * mean * s1.w + (float)N_ * mean * mean) * rc;
        o.w = fmaf((u.w - mean) * rsqrtf(var + 1e-5f), scale[d0 + 3], shift[d0 + 3]) * m;
    }
    reinterpret_cast<float4*>(out)[t] = o;
}

extern "C" void kernel_launch(void* const* d_in, const int* in_sizes, int n_in,
                              void* d_out, int out_size) {
    const float* emb   = (const float*)d_in[0];
    const float* dists = (const float*)d_in[1];
    const int*   eidx  = (const int*)d_in[2];
    const float* mask  = (const float*)d_in[3];
    const float* W0 = (const float*)d_in[4];
    const float* b0 = (const float*)d_in[5];
    const float* W1 = (const float*)d_in[6];
    const float* b1 = (const float*)d_in[7];
    const float* W2 = (const float*)d_in[8];
    const float* b2 = (const float*)d_in[9];
    const float* scale = (const float*)d_in[10];
    const float* shift = (const float*)d_in[11];
    float* out = (float*)d_out;

    int smc = 148;
    cudaDeviceGetAttribute(&smc, cudaDevAttrMultiProcessorCount, 0);

    cudaFuncSetAttribute(mpnn_msg_kernel,
                         cudaFuncAttributeMaxDynamicSharedMemorySize, SMEM_BYTES);

    init_stats_kernel<<<B_, 256>>>(mask);
    embh_kernel<<<B_ * N_ * 16 / 256, 256>>>(emb, mask);
    selfc_kernel<<<B_ * N_ / 16, 256>>>(emb, mask, W0, b0);
    mpnn_msg_kernel<<<2 * smc, 256, SMEM_BYTES>>>(emb, dists, eidx, mask,
                                                  W0, b0, W1, b1, W2, b2);
    norm_kernel<<<(B_ * N_ * D_ / 4 + 255) / 256, 256>>>(mask, scale, shift, out);
}